// round 11
// baseline (speedup 1.0000x reference)
#include <cuda_runtime.h>
#include <cuda.h>
#include <cstdint>

// HiPoNet collapse: P = 0.5*(Wm/colsum) + 0.5*I is column-stochastic, so
// 1^T P^t = 1^T and mean_n(P^t X) = mean_n(X) exactly. Output:
//   out[b, w*160 + k*32 + d] = mean_n(pc[b,n,d]) * alphas[w,d], k=0..4.
//
// R11: R10 (TMA sector gather) with the alignment bug fixed: the SMEM
// destination for cp.async.bulk.tensor must be 128B-aligned, but extern
// dynamic smem only guarantees 16B. Now the mbarrier (8B) and the 64KB
// data region (1024B) are carved out of an over-allocated buffer with
// explicit runtime rounding. Everything else identical to R10; fallback
// is the exact R7 LDG kernel.

#define NPTS   2048
#define DIM    32
#define NW     4
#define NCOLL  5
#define FOUT   (NW * NCOLL * DIM)        // 640 per batch
#define BLK    512
#define DQ     8                         // dims per block (one 32B sector)
#define NCHUNK 8                         // TMA boxes per block
#define CROWS  (NPTS / NCHUNK)           // 256 rows per box
#define CHBYTES (CROWS * DQ * 4)         // 8192 bytes per box
#define DATA_BYTES (NCHUNK * CHBYTES)    // 65536
#define SMEM_TOTAL (DATA_BYTES + 2048)   // slack for alignment + mbar

__device__ __forceinline__ float4 f4add(float4 a, float4 b) {
    return make_float4(a.x + b.x, a.y + b.y, a.z + b.z, a.w + b.w);
}
__device__ __forceinline__ float4 f4shfl_xor(float4 v, int m) {
    v.x += __shfl_xor_sync(0xffffffffu, v.x, m);
    v.y += __shfl_xor_sync(0xffffffffu, v.y, m);
    v.z += __shfl_xor_sync(0xffffffffu, v.z, m);
    v.w += __shfl_xor_sync(0xffffffffu, v.w, m);
    return v;
}
__device__ __forceinline__ uint32_t smem_u32(const void* p) {
    uint32_t a;
    asm("{ .reg .u64 t; cvta.to.shared.u64 t, %1; cvt.u32.u64 %0, t; }"
        : "=r"(a) : "l"(p));
    return a;
}

// ---------------- shared epilogue (identical math to R7) ----------------
__device__ __forceinline__ void epilogue(float4 s, int t, int half,
                                         int b, int dq,
                                         const float* __restrict__ alphas,
                                         float* __restrict__ out,
                                         float sm[16][DQ])
{
    __shared__ float mean_s[DQ];
    __shared__ float al[NW * DQ];
    if (t < NW * DQ)
        al[t] = alphas[(t >> 3) * DIM + dq * DQ + (t & 7)];

    s = f4shfl_xor(s, 2);
    s = f4shfl_xor(s, 4);
    s = f4shfl_xor(s, 8);
    s = f4shfl_xor(s, 16);
    if ((t & 31) < 2)
        *(float4*)&sm[t >> 5][half * 4] = s;
    __syncthreads();

    if (t < DQ) {
        float acc = 0.f;
        #pragma unroll
        for (int i = 0; i < 16; ++i) acc += sm[i][t];
        mean_s[t] = acc * (1.0f / (float)NPTS);
    }
    __syncthreads();

    if (t < NW * NCOLL * DQ) {           // 160 disjoint outputs
        const int ww  = t / (NCOLL * DQ);
        const int rem = t - ww * (NCOLL * DQ);
        const int kk  = rem >> 3;
        const int dl  = rem & 7;
        out[b * FOUT + ww * (NCOLL * DIM) + kk * DIM + dq * DQ + dl] =
            mean_s[dl] * al[ww * DQ + dl];
    }
}

// ---------------- R11: TMA gather kernel (aligned) ----------------
__global__ __launch_bounds__(BLK, 1)
void hiponet_tma_kernel(const __grid_constant__ CUtensorMap tmap,
                        const float* __restrict__ alphas,
                        float* __restrict__ out)
{
    extern __shared__ char smem_raw[];
    __shared__ float smw[16][DQ];
    const int b    = blockIdx.x >> 2;    // batch 0..3
    const int dq   = blockIdx.x & 3;     // dim quarter 0..3
    const int t    = threadIdx.x;        // 0..511
    const int half = t & 1;
    const int r    = t >> 1;             // 0..255 (local row within a chunk)

    // explicit alignment: data 1024B-aligned (TMA needs >=128B), mbar 8B
    const uint32_t base0 = smem_u32(smem_raw);
    const uint32_t data  = (base0 + 1023u) & ~1023u;
    const uint32_t mbar  = data + (uint32_t)DATA_BYTES;   // 8B-aligned

    if (t == 0) {
        asm volatile("mbarrier.init.shared.b64 [%0], 1;" :: "r"(mbar) : "memory");
    }
    __syncthreads();

    if (t == 0) {
        asm volatile("mbarrier.arrive.expect_tx.shared.b64 _, [%0], %1;"
                     :: "r"(mbar), "r"((uint32_t)DATA_BYTES) : "memory");
        #pragma unroll
        for (int k = 0; k < NCHUNK; ++k) {
            asm volatile(
                "cp.async.bulk.tensor.3d.shared::cta.global.tile"
                ".mbarrier::complete_tx::bytes [%0], [%1, {%2, %3, %4}], [%5];"
                :: "r"(data + (uint32_t)(k * CHBYTES)),
                   "l"(&tmap),
                   "r"(dq * DQ), "r"(k * CROWS), "r"(b),
                   "r"(mbar)
                : "memory");
        }
    }

    // wait (parity 0, fresh barrier each launch)
    {
        uint32_t done;
        do {
            asm volatile(
                "{\n\t.reg .pred p;\n\t"
                "mbarrier.try_wait.parity.shared.b64 p, [%1], 0;\n\t"
                "selp.b32 %0, 1, 0, p;\n\t}"
                : "=r"(done) : "r"(mbar) : "memory");
        } while (!done);
    }

    // ---- conflict-free LDS.128 reduce: one float4 per chunk per thread ----
    const int idx = r * 2 + half;        // float4 index within a chunk
    float4 v[NCHUNK];
    #pragma unroll
    for (int k = 0; k < NCHUNK; ++k) {
        const uint32_t a = data + (uint32_t)(k * CHBYTES + idx * 16);
        asm volatile("ld.shared.v4.f32 {%0,%1,%2,%3}, [%4];"
                     : "=f"(v[k].x), "=f"(v[k].y), "=f"(v[k].z), "=f"(v[k].w)
                     : "r"(a));
    }
    float4 s = f4add(f4add(f4add(v[0], v[1]), f4add(v[2], v[3])),
                     f4add(f4add(v[4], v[5]), f4add(v[6], v[7])));

    epilogue(s, t, half, b, dq, alphas, out, smw);
}

// ---------------- fallback: exact R7 LDG kernel ----------------
#define RPP (BLK / 2)                    // 256 rows per pass
#define LPT (NPTS / RPP)                 // 8 loads per thread

__global__ __launch_bounds__(BLK, 1)
void hiponet_kernel(const float* __restrict__ pc,
                    const float* __restrict__ alphas,
                    float* __restrict__ out)
{
    __shared__ float smw[16][DQ];
    const int b    = blockIdx.x >> 2;
    const int dq   = blockIdx.x & 3;
    const int t    = threadIdx.x;
    const int half = t & 1;
    const int r    = t >> 1;

    const float4* __restrict__ base =
        (const float4*)pc + ((size_t)b * NPTS + r) * (DIM / 4) + dq * 2 + half;

    float4 v[LPT];
    #pragma unroll
    for (int k = 0; k < LPT; ++k)
        v[k] = base[(size_t)k * RPP * (DIM / 4)];
    float4 s = f4add(f4add(f4add(v[0], v[1]), f4add(v[2], v[3])),
                     f4add(f4add(v[4], v[5]), f4add(v[6], v[7])));

    epilogue(s, t, half, b, dq, alphas, out, smw);
}

// ---------------- host ----------------
typedef CUresult (*PFN_encodeTiled)(
    CUtensorMap*, CUtensorMapDataType, cuuint32_t, void*,
    const cuuint64_t*, const cuuint64_t*, const cuuint32_t*, const cuuint32_t*,
    CUtensorMapInterleave, CUtensorMapSwizzle, CUtensorMapL2promotion,
    CUtensorMapFloatOOBfill);

extern "C" void kernel_launch(void* const* d_in, const int* in_sizes, int n_in,
                              void* d_out, int out_size)
{
    const float* pc     = (const float*)d_in[0];  // [4, 2048, 32] fp32
    // d_in[1] = sigma: output is invariant to the diffusion operator
    const float* alphas = (const float*)d_in[2];  // [4, 32] fp32
    float* out = (float*)d_out;                   // [4, 640] fp32

    PFN_encodeTiled enc = nullptr;
    cudaDriverEntryPointQueryResult qr = cudaDriverEntryPointSymbolNotFound;
    cudaGetDriverEntryPoint("cuTensorMapEncodeTiled", (void**)&enc,
                            cudaEnableDefault, &qr);

    bool ok = false;
    CUtensorMap tmap;
    if (enc && qr == cudaDriverEntryPointSuccess) {
        cuuint64_t dims[3]    = {DIM, NPTS, 4};            // [32, 2048, 4]
        cuuint64_t strides[2] = {DIM * 4ull,               // 128 B row stride
                                 (cuuint64_t)NPTS * DIM * 4ull};
        cuuint32_t box[3]     = {DQ, CROWS, 1};            // [8, 256, 1]
        cuuint32_t es[3]      = {1, 1, 1};
        CUresult r = enc(&tmap, CU_TENSOR_MAP_DATA_TYPE_FLOAT32, 3, (void*)pc,
                         dims, strides, box, es,
                         CU_TENSOR_MAP_INTERLEAVE_NONE,
                         CU_TENSOR_MAP_SWIZZLE_NONE,
                         CU_TENSOR_MAP_L2_PROMOTION_L2_128B,
                         CU_TENSOR_MAP_FLOAT_OOB_FILL_NONE);
        ok = (r == CUDA_SUCCESS);
    }

    if (ok) {
        cudaFuncSetAttribute(hiponet_tma_kernel,
                             cudaFuncAttributeMaxDynamicSharedMemorySize,
                             SMEM_TOTAL);
        hiponet_tma_kernel<<<16, BLK, SMEM_TOTAL>>>(tmap, alphas, out);
    } else {
        hiponet_kernel<<<16, BLK>>>(pc, alphas, out);
    }
}

// round 12
// speedup vs baseline: 1.0046x; 1.0046x over previous
#include <cuda_runtime.h>

// HiPoNet collapse: P = 0.5*(Wm/colsum) + 0.5*I is column-stochastic, so
// 1^T P^t = 1^T and mean_n(P^t X) = mean_n(X) exactly. Output:
//   out[b, w*160 + k*32 + d] = mean_n(pc[b,n,d]) * alphas[w,d], k=0..4.
//
// R12: row partition + waiting-free combining. Graph = memset(out,0) node
// + one kernel node. Grid=16 = (batch b, row-quarter rq). Each block reads
// 512 FULL 128B rows (512 L1tex wavefronts/SM vs 2048 for the sector
// partition), reduces to a 32-dim partial, and fires 640 no-return
// atomicAdds (RED.E.ADD.F32) of partial_mean*alpha into out. Producers
// never wait on each other: the only combining cost is the RED issue and
// the memset node. (Atomics/cluster/flags with WAITING all measured
// slower; TMA gather measured slower; this is the zero-wait variant.)

#define NPTS   2048
#define DIM    32
#define NW     4
#define NCOLL  5
#define FOUT   (NW * NCOLL * DIM)        // 640 per batch
#define RQ     4                         // row quarters per batch
#define BLK    512
#define ROWS   (NPTS / RQ)               // 512 rows per block
#define QPR    (DIM / 4)                 // 8 float4 per row
#define LPT    8                         // loads per thread

__device__ __forceinline__ float4 f4add(float4 a, float4 b) {
    return make_float4(a.x + b.x, a.y + b.y, a.z + b.z, a.w + b.w);
}

__global__ __launch_bounds__(BLK, 1)
void hiponet_kernel(const float* __restrict__ pc,
                    const float* __restrict__ alphas,
                    float* __restrict__ out)
{
    const int b  = blockIdx.x >> 2;      // batch 0..3
    const int r4 = blockIdx.x & 3;       // row quarter 0..3
    const int t  = threadIdx.x;          // 0..511
    const int q  = t & (QPR - 1);        // float4 slot in row, 0..7
    const int rg = t >> 3;               // row group, 0..63

    __shared__ float sm[16][DIM];        // per-warp partials
    __shared__ float mean_s[DIM];
    __shared__ float al[NW * DIM];

    if (t < NW * DIM) al[t] = alphas[t]; // overlaps DRAM latency

    // ---- 512 full rows, 8 independent LDG.128 per thread ----
    const float4* __restrict__ base =
        (const float4*)(pc + ((size_t)b * NPTS + r4 * ROWS) * DIM);

    float4 v[LPT];
    #pragma unroll
    for (int k = 0; k < LPT; ++k)
        v[k] = base[(size_t)(rg + (k << 6)) * QPR + q];
    float4 s = f4add(f4add(f4add(v[0], v[1]), f4add(v[2], v[3])),
                     f4add(f4add(v[4], v[5]), f4add(v[6], v[7])));

    // warp reduce over the 4 row-groups in this warp (lane bits 3,4)
    #pragma unroll
    for (int m = 8; m <= 16; m <<= 1) {
        s.x += __shfl_xor_sync(0xffffffffu, s.x, m);
        s.y += __shfl_xor_sync(0xffffffffu, s.y, m);
        s.z += __shfl_xor_sync(0xffffffffu, s.z, m);
        s.w += __shfl_xor_sync(0xffffffffu, s.w, m);
    }
    if ((t & 31) < QPR)                  // lanes 0..7: warp's 32-row sums
        *(float4*)&sm[t >> 5][q * 4] = s;
    __syncthreads();

    if (t < DIM) {                       // d = t: sum 16 warp partials
        float acc = 0.f;
        #pragma unroll
        for (int i = 0; i < 16; ++i) acc += sm[i][t];
        mean_s[t] = acc * (1.0f / (float)NPTS);
    }
    __syncthreads();

    // ---- waiting-free combine: 640 no-return RED.E.ADD.F32 ----
    float* __restrict__ ob = out + b * FOUT;
    {
        // i = t (all 512) and i = t + 512 (first 128 threads)
        const int w0 = t / (NCOLL * DIM);
        const int d0 = t & 31;
        atomicAdd(&ob[t], mean_s[d0] * al[w0 * DIM + d0]);
        if (t < FOUT - BLK) {
            const int i  = t + BLK;
            const int w1 = i / (NCOLL * DIM);
            const int d1 = i & 31;
            atomicAdd(&ob[i], mean_s[d1] * al[w1 * DIM + d1]);
        }
    }
}

extern "C" void kernel_launch(void* const* d_in, const int* in_sizes, int n_in,
                              void* d_out, int out_size)
{
    const float* pc     = (const float*)d_in[0];  // [4, 2048, 32] fp32
    // d_in[1] = sigma: output is invariant to the diffusion operator
    const float* alphas = (const float*)d_in[2];  // [4, 32] fp32
    float* out = (float*)d_out;                   // [4, 640] fp32

    // out is poisoned to 0xAA; RED-combining needs it zeroed. Async memset
    // is graph-capturable (becomes a memset node ordered before the kernel).
    cudaMemsetAsync(d_out, 0, (size_t)out_size * sizeof(float), 0);
    hiponet_kernel<<<16, BLK>>>(pc, alphas, out);
}

// round 13
// speedup vs baseline: 1.0093x; 1.0047x over previous
#include <cuda_runtime.h>

// HiPoNet collapse: P = 0.5*(Wm/colsum) + 0.5*I is column-stochastic, so
// 1^T P^t = 1^T and mean_n(P^t X) = mean_n(X) exactly. Output:
//   out[b, w*160 + k*32 + d] = mean_n(pc[b,n,d]) * alphas[w,d], k=0..4.
//
// R13: R12 (row partition + zero-wait RED combining + memset node) with
// the L1tex wavefront drain halved again: grid=32 = (batch, 8 row-chunks),
// 256 threads/block -> each block reads 256 FULL 128B rows (256 line-
// wavefronts/SM vs 512 in R12, vs 2048 in the zero-comm sector layout).
// 8 independent LDG.128/thread; 8-warp reduce tail; 640 no-return
// RED.E.ADD.F32 per block. Graph = memset(out) node + kernel node.

#define NPTS   2048
#define DIM    32
#define NW     4
#define NCOLL  5
#define FOUT   (NW * NCOLL * DIM)        // 640 per batch
#define RC     8                         // row chunks per batch
#define BLK    256
#define ROWS   (NPTS / RC)               // 256 rows per block
#define QPR    (DIM / 4)                 // 8 float4 per row
#define NWARP  (BLK / 32)                // 8 warps
#define LPT    8                         // loads per thread

__device__ __forceinline__ float4 f4add(float4 a, float4 b) {
    return make_float4(a.x + b.x, a.y + b.y, a.z + b.z, a.w + b.w);
}

__global__ __launch_bounds__(BLK, 1)
void hiponet_kernel(const float* __restrict__ pc,
                    const float* __restrict__ alphas,
                    float* __restrict__ out)
{
    const int b  = blockIdx.x >> 3;      // batch 0..3
    const int rc = blockIdx.x & 7;       // row chunk 0..7
    const int t  = threadIdx.x;          // 0..255
    const int q  = t & (QPR - 1);        // float4 slot in row, 0..7
    const int rg = t >> 3;               // row group, 0..31

    __shared__ float sm[NWARP][DIM];     // per-warp partials
    __shared__ float mean_s[DIM];
    __shared__ float al[NW * DIM];

    if (t < NW * DIM) al[t] = alphas[t]; // overlaps DRAM latency

    // ---- 256 full rows, 8 independent LDG.128 per thread ----
    const float4* __restrict__ base =
        (const float4*)(pc + ((size_t)b * NPTS + rc * ROWS) * DIM);

    float4 v[LPT];
    #pragma unroll
    for (int k = 0; k < LPT; ++k)
        v[k] = base[(size_t)(rg + (k << 5)) * QPR + q];
    float4 s = f4add(f4add(f4add(v[0], v[1]), f4add(v[2], v[3])),
                     f4add(f4add(v[4], v[5]), f4add(v[6], v[7])));

    // warp reduce over the 4 row-groups in this warp (lane bits 3,4)
    #pragma unroll
    for (int m = 8; m <= 16; m <<= 1) {
        s.x += __shfl_xor_sync(0xffffffffu, s.x, m);
        s.y += __shfl_xor_sync(0xffffffffu, s.y, m);
        s.z += __shfl_xor_sync(0xffffffffu, s.z, m);
        s.w += __shfl_xor_sync(0xffffffffu, s.w, m);
    }
    if ((t & 31) < QPR)                  // lanes 0..7: warp's 32-row sums
        *(float4*)&sm[t >> 5][q * 4] = s;
    __syncthreads();

    if (t < DIM) {                       // d = t: sum 8 warp partials
        float acc = ((sm[0][t] + sm[1][t]) + (sm[2][t] + sm[3][t]))
                  + ((sm[4][t] + sm[5][t]) + (sm[6][t] + sm[7][t]));
        mean_s[t] = acc * (1.0f / (float)NPTS);
    }
    __syncthreads();

    // ---- zero-wait combine: 640 no-return RED.E.ADD.F32 per block ----
    float* __restrict__ ob = out + b * FOUT;
    #pragma unroll
    for (int i = t; i < FOUT; i += BLK) {  // i = t, t+256 (+128 tail)
        const int w = i / (NCOLL * DIM);
        const int d = i & 31;
        atomicAdd(&ob[i], mean_s[d] * al[w * DIM + d]);
    }
}

extern "C" void kernel_launch(void* const* d_in, const int* in_sizes, int n_in,
                              void* d_out, int out_size)
{
    const float* pc     = (const float*)d_in[0];  // [4, 2048, 32] fp32
    // d_in[1] = sigma: output is invariant to the diffusion operator
    const float* alphas = (const float*)d_in[2];  // [4, 32] fp32
    float* out = (float*)d_out;                   // [4, 640] fp32

    // out poisoned to 0xAA; RED combining requires zero-init each replay.
    cudaMemsetAsync(d_out, 0, (size_t)out_size * sizeof(float), 0);
    hiponet_kernel<<<4 * RC, BLK>>>(pc, alphas, out);
}

// round 14
// speedup vs baseline: 1.0483x; 1.0386x over previous
#include <cuda_runtime.h>

// HiPoNet collapse: P = 0.5*(Wm/colsum) + 0.5*I is column-stochastic, so
// 1^T P^t = 1^T and mean_n(P^t X) = mean_n(X) exactly. Output:
//   out[b, w*160 + k*32 + d] = mean_n(pc[b,n,d]) * alphas[w,d], k=0..4.
//
// R14: R13 (row partition + zero-wait RED + memset node) tuned:
//  - BLK 512 (16 warps hide DRAM fill; 4 independent LDG.128/thread)
//  - per-block SKEWED RED order (rc*80 offset) so the 8 contributor
//    blocks of a batch sweep disjoint windows of the 640-wide output
//    at any instant -> L2 atomic queueing ~8x lower on the drain
//  - grid=32 = (batch, 8 row chunks), 256 full 128B rows per block
//    (256 L1tex line-wavefronts/SM).

#define NPTS   2048
#define DIM    32
#define NW     4
#define NCOLL  5
#define FOUT   (NW * NCOLL * DIM)        // 640 per batch
#define RC     8                         // row chunks per batch
#define BLK    512
#define ROWS   (NPTS / RC)               // 256 rows per block
#define QPR    (DIM / 4)                 // 8 float4 per row
#define NWARP  (BLK / 32)                // 16 warps
#define LPT    4                         // loads per thread

__device__ __forceinline__ float4 f4add(float4 a, float4 b) {
    return make_float4(a.x + b.x, a.y + b.y, a.z + b.z, a.w + b.w);
}

__global__ __launch_bounds__(BLK, 1)
void hiponet_kernel(const float* __restrict__ pc,
                    const float* __restrict__ alphas,
                    float* __restrict__ out)
{
    const int b  = blockIdx.x >> 3;      // batch 0..3
    const int rc = blockIdx.x & 7;       // row chunk 0..7
    const int t  = threadIdx.x;          // 0..511
    const int q  = t & (QPR - 1);        // float4 slot in row, 0..7
    const int rg = t >> 3;               // row group, 0..63

    __shared__ float sm[NWARP][DIM];     // per-warp partials
    __shared__ float mean_s[DIM];
    __shared__ float al[NW * DIM];

    if (t < NW * DIM) al[t] = alphas[t]; // overlaps DRAM latency

    // ---- 256 full rows, 4 independent LDG.128 per thread ----
    const float4* __restrict__ base =
        (const float4*)(pc + ((size_t)b * NPTS + rc * ROWS) * DIM);

    float4 v[LPT];
    #pragma unroll
    for (int k = 0; k < LPT; ++k)
        v[k] = base[(size_t)(rg + (k << 6)) * QPR + q];
    float4 s = f4add(f4add(v[0], v[1]), f4add(v[2], v[3]));

    // warp reduce over the 4 row-groups in this warp (lane bits 3,4)
    #pragma unroll
    for (int m = 8; m <= 16; m <<= 1) {
        s.x += __shfl_xor_sync(0xffffffffu, s.x, m);
        s.y += __shfl_xor_sync(0xffffffffu, s.y, m);
        s.z += __shfl_xor_sync(0xffffffffu, s.z, m);
        s.w += __shfl_xor_sync(0xffffffffu, s.w, m);
    }
    if ((t & 31) < QPR)                  // lanes 0..7: warp's 16-row sums
        *(float4*)&sm[t >> 5][q * 4] = s;
    __syncthreads();

    if (t < DIM) {                       // d = t: sum 16 warp partials
        float acc = 0.f;
        #pragma unroll
        for (int i = 0; i < 16; ++i) acc += sm[i][t];
        mean_s[t] = acc * (1.0f / (float)NPTS);
    }
    __syncthreads();

    // ---- zero-wait combine: 640 REDs, block-skewed address order ----
    float* __restrict__ ob = out + b * FOUT;
    const int skew = rc * (FOUT / RC);   // 80-element disjoint windows
    #pragma unroll
    for (int j = t; j < FOUT; j += BLK) {
        int i = j + skew;
        if (i >= FOUT) i -= FOUT;
        const int w = i / (NCOLL * DIM);
        const int d = i & 31;
        atomicAdd(&ob[i], mean_s[d] * al[w * DIM + d]);
    }
}

extern "C" void kernel_launch(void* const* d_in, const int* in_sizes, int n_in,
                              void* d_out, int out_size)
{
    const float* pc     = (const float*)d_in[0];  // [4, 2048, 32] fp32
    // d_in[1] = sigma: output is invariant to the diffusion operator
    const float* alphas = (const float*)d_in[2];  // [4, 32] fp32
    float* out = (float*)d_out;                   // [4, 640] fp32

    // out poisoned to 0xAA; RED combining requires zero-init each replay.
    cudaMemsetAsync(d_out, 0, (size_t)out_size * sizeof(float), 0);
    hiponet_kernel<<<4 * RC, BLK>>>(pc, alphas, out);
}